// round 12
// baseline (speedup 1.0000x reference)
#include <cuda_runtime.h>

#define NN 100000
#define EE 1600000
#define DD 64
#define GG 64
#define OUTC 10
#define NB ((NN + 255) / 256)   // 391 scan blocks

// ---- scratch ----
__device__ int    g_is64;
__device__ int    g_batch[NN];
__device__ int    g_deg[NN];      // zeroed by trailing fold (and module load)
__device__ int    g_cursor[NN];   // zeroed by trailing fold (and module load)
__device__ int    g_rowstart[NN]; // block-local exclusive prefix
__device__ int    g_bsum[NB];
__device__ int    g_bsum_sc[NB];
__device__ int    g_adj[EE];
__device__ float4 g_agg[(size_t)NN * (DD / 4)];
__device__ float4 g_h0 [(size_t)NN * (DD / 4)];
__device__ float4 g_h1 [(size_t)NN * (DD / 4)];
__device__ float  g_pool[GG * DD];

__device__ __forceinline__ int load_idx(const void* p, size_t i, int is64) {
    return is64 ? (int)((const long long*)p)[i] : ((const int*)p)[i];
}

// packed f32x2 FMA: d = a*b + d on both lanes (SASS FFMA2; 2 FMAs/instr,
// only reachable via PTX fma.rn.f32x2 per SASS_QUICKREF)
__device__ __forceinline__ void ffma2(unsigned long long& d,
                                      unsigned long long a,
                                      unsigned long long b) {
    asm("fma.rn.f32x2 %0, %1, %2, %0;" : "+l"(d) : "l"(a), "l"(b));
}

// ---- launch 1: dtype detect + batch convert + degree histogram -------------
__global__ void prep_deg_kernel(const void* __restrict__ ei,
                                const void* __restrict__ bat) {
    __shared__ int s_is64;
    if (threadIdx.x == 0) {
        const unsigned int* w = (const unsigned int*)ei;
        int is64 = 1;
        for (int i = 0; i < 16; i++)
            if (w[2 * i + 1] != 0u) { is64 = 0; break; }
        s_is64 = is64;
        if (blockIdx.x == 0) g_is64 = is64;
    }
    __syncthreads();
    int is64 = s_is64;
    int e = blockIdx.x * blockDim.x + threadIdx.x;
    if (e < NN) g_batch[e] = load_idx(bat, e, is64);
    if (e < EE) atomicAdd(&g_deg[load_idx(ei, (size_t)EE + e, is64)], 1);
}

// ---- launch 2: block-local exclusive scan ----------------------------------
__global__ void scan_block_kernel() {
    __shared__ int s[256];
    int tid = threadIdx.x;
    int i = blockIdx.x * 256 + tid;
    int v = (i < NN) ? g_deg[i] : 0;
    s[tid] = v;
    __syncthreads();
    #pragma unroll
    for (int off = 1; off < 256; off <<= 1) {
        int t = (tid >= off) ? s[tid - off] : 0;
        __syncthreads();
        s[tid] += t;
        __syncthreads();
    }
    if (i < NN) g_rowstart[i] = s[tid] - v;
    if (tid == 255) g_bsum[blockIdx.x] = s[255];
}

// ---- launch 3: scan the 391 block sums -------------------------------------
__global__ void scan_top_kernel() {
    __shared__ int s[512];
    int tid = threadIdx.x;
    int v = (tid < NB) ? g_bsum[tid] : 0;
    s[tid] = v;
    __syncthreads();
    #pragma unroll
    for (int off = 1; off < 512; off <<= 1) {
        int t = (tid >= off) ? s[tid - off] : 0;
        __syncthreads();
        s[tid] += t;
        __syncthreads();
    }
    if (tid < NB) g_bsum_sc[tid] = s[tid] - v;
}

// ---- launch 4: adjacency fill (profiled R9: 25us, 68% L2 — near bound) -----
__global__ void csr_fill_kernel(const void* __restrict__ ei) {
    int e = blockIdx.x * blockDim.x + threadIdx.x;
    if (e < EE) {
        int is64 = g_is64;
        int src = load_idx(ei, e, is64);
        int dst = load_idx(ei, (size_t)EE + e, is64);
        int pos = atomicAdd(&g_cursor[dst], 1);
        g_adj[g_rowstart[dst] + g_bsum_sc[dst >> 8] + pos] = src;
    }
}

// ---- gather-mean: one warp per node, lane owns float2, unroll x8 (MLP 8) ---
__global__ void gather_kernel(int sel, const float* __restrict__ x) {
    int gtid = blockIdx.x * blockDim.x + threadIdx.x;
    int node = gtid >> 5;
    if (node >= NN) return;
    int lane = threadIdx.x & 31;

    const float2* hin = (sel == 0) ? (const float2*)x
                       : (sel == 1) ? (const float2*)g_h0 : (const float2*)g_h1;

    int rs = g_rowstart[node] + g_bsum_sc[node >> 8];
    int re = (node + 1 < NN)
           ? g_rowstart[node + 1] + g_bsum_sc[(node + 1) >> 8] : EE;
    float ax = 0.f, ay = 0.f;
    int e = rs;
    for (; e + 8 <= re; e += 8) {
        int s0 = g_adj[e+0], s1 = g_adj[e+1], s2 = g_adj[e+2], s3 = g_adj[e+3];
        int s4 = g_adj[e+4], s5 = g_adj[e+5], s6 = g_adj[e+6], s7 = g_adj[e+7];
        float2 v0 = hin[(size_t)s0 * 32 + lane];
        float2 v1 = hin[(size_t)s1 * 32 + lane];
        float2 v2 = hin[(size_t)s2 * 32 + lane];
        float2 v3 = hin[(size_t)s3 * 32 + lane];
        float2 v4 = hin[(size_t)s4 * 32 + lane];
        float2 v5 = hin[(size_t)s5 * 32 + lane];
        float2 v6 = hin[(size_t)s6 * 32 + lane];
        float2 v7 = hin[(size_t)s7 * 32 + lane];
        ax += (v0.x + v1.x) + (v2.x + v3.x) + ((v4.x + v5.x) + (v6.x + v7.x));
        ay += (v0.y + v1.y) + (v2.y + v3.y) + ((v4.y + v5.y) + (v6.y + v7.y));
    }
    for (; e < re; e++) {
        int s = g_adj[e];
        float2 v = hin[(size_t)s * 32 + lane];
        ax += v.x; ay += v.y;
    }
    float inv = 1.0f / (float)max(re - rs, 1);
    ((float2*)g_agg)[(size_t)node * 32 + lane] = make_float2(ax * inv, ay * inv);
}

// ---- register-tiled linear with k-packed FFMA2 -----------------------------
// out = relu([agg|h] @ [Wl;Wr] + bl), two k=64 passes.
// Accumulators are f32x2: lane0 sums even-k, lane1 odd-k; one FADD at the end.
// sA2[kk][r] = (A[r][2kk], A[r][2kk+1])  (adjacent in source row -> free pack)
// sW2[kk][c] = (W[2kk][c], W[2kk+1][c])  (packed during staging)
// Inner loop per kk: 4x LDS.128 + 16 FFMA2 (was 4x LDS.128 + 32 FFMA).
__global__ void linear_kernel(int sel, const float* __restrict__ x,
                              const float* __restrict__ Wl,
                              const float* __restrict__ bl,
                              const float* __restrict__ Wr) {
    __shared__ __align__(16) float2 sA2[DD / 2][DD + 2];
    __shared__ __align__(16) float2 sW2[DD / 2][DD];
    __shared__ float sb[DD];

    const float* hin  = (sel == 0) ? x
                       : (sel == 1) ? (const float*)g_h0 : (const float*)g_h1;
    float*       hout = (sel == 0) ? (float*)g_h0
                       : (sel == 1) ? (float*)g_h1 : (float*)g_h0;

    int tid  = threadIdx.x;
    int base = blockIdx.x * 64;
    int tc = tid & 15;
    int tr = tid >> 4;
    if (tid < DD) sb[tid] = bl[tid];

    if (sel == 2 && tid < 64) {          // trailing state-reset fold
        int n = base + tid;
        if (n < NN) { g_deg[n] = 0; g_cursor[n] = 0; }
    }

    unsigned long long accp[4][4];
    #pragma unroll
    for (int i = 0; i < 4; i++)
        #pragma unroll
        for (int j = 0; j < 4; j++) accp[i][j] = 0ull;

    int r_st   = tid >> 2;               // staging row 0..63
    int row_st = base + r_st;
    int k4b    = (tid & 3) * 4;          // staging k4 base

    #pragma unroll
    for (int pass = 0; pass < 2; pass++) {
        const float* A = (pass == 0) ? (const float*)g_agg : hin;
        const float* W = (pass == 0) ? Wl : Wr;
        // stage W packed along k: sW2[k>>1][col].{x|y} = W[k][col]
        for (int i = tid; i < DD * DD; i += 256) {
            int k = i >> 6, col = i & 63;
            ((float*)&sW2[k >> 1][col])[k & 1] = W[i];
        }
        // stage A: adjacent k-pairs of each row -> float2, transposed layout
        #pragma unroll
        for (int j = 0; j < 4; j++) {
            int k4 = k4b + j;
            float4 v = make_float4(0.f, 0.f, 0.f, 0.f);
            if (row_st < NN) v = ((const float4*)A)[(size_t)row_st * (DD/4) + k4];
            sA2[k4 * 2 + 0][r_st] = make_float2(v.x, v.y);
            sA2[k4 * 2 + 1][r_st] = make_float2(v.z, v.w);
        }
        __syncthreads();
        #pragma unroll 8
        for (int kk = 0; kk < DD / 2; kk++) {
            ulonglong2 a01 = *(const ulonglong2*)&sA2[kk][tr * 4 + 0];
            ulonglong2 a23 = *(const ulonglong2*)&sA2[kk][tr * 4 + 2];
            ulonglong2 w01 = *(const ulonglong2*)&sW2[kk][tc * 4 + 0];
            ulonglong2 w23 = *(const ulonglong2*)&sW2[kk][tc * 4 + 2];
            unsigned long long av[4] = { a01.x, a01.y, a23.x, a23.y };
            unsigned long long wv[4] = { w01.x, w01.y, w23.x, w23.y };
            #pragma unroll
            for (int i = 0; i < 4; i++)
                #pragma unroll
                for (int j = 0; j < 4; j++)
                    ffma2(accp[i][j], av[i], wv[j]);
        }
        __syncthreads();
    }

    // epilogue: horizontal add, +bias, relu, float4 store
    #pragma unroll
    for (int i = 0; i < 4; i++) {
        int row = base + tr * 4 + i;
        if (row < NN) {
            float s[4];
            #pragma unroll
            for (int j = 0; j < 4; j++) {
                union { unsigned long long u; float2 f; } cv;
                cv.u = accp[i][j];
                s[j] = cv.f.x + cv.f.y;
            }
            float4 o;
            o.x = fmaxf(s[0] + sb[tc * 4 + 0], 0.f);
            o.y = fmaxf(s[1] + sb[tc * 4 + 1], 0.f);
            o.z = fmaxf(s[2] + sb[tc * 4 + 2], 0.f);
            o.w = fmaxf(s[3] + sb[tc * 4 + 3], 0.f);
            *(float4*)&hout[(size_t)row * DD + tc * 4] = o;
        }
    }
}

// ---- global mean pool (batch sorted -> binary search) ----------------------
__global__ void pool_kernel() {
    int g = blockIdx.x;
    int col = threadIdx.x;
    int a = 0, b = NN;
    while (a < b) { int m = (a + b) >> 1; if (g_batch[m] < g) a = m + 1; else b = m; }
    int start = a;
    b = NN;
    while (a < b) { int m = (a + b) >> 1; if (g_batch[m] < g + 1) a = m + 1; else b = m; }
    int end = a;
    float acc = 0.f;
    const float* h = (const float*)g_h0;
    for (int n = start; n < end; n++) acc += h[(size_t)n * DD + col];
    g_pool[g * DD + col] = acc / fmaxf((float)(end - start), 1.f);
}

// ---- final MLP -------------------------------------------------------------
__global__ void mlp_kernel(const float* __restrict__ l0W,
                           const float* __restrict__ l0b,
                           const float* __restrict__ outW,
                           const float* __restrict__ outb,
                           float* __restrict__ out) {
    __shared__ float sg[DD];
    __shared__ float sh[DD];
    int gi = blockIdx.x, t = threadIdx.x;
    sg[t] = g_pool[gi * DD + t];
    __syncthreads();
    float acc = l0b[t];
    #pragma unroll
    for (int k = 0; k < DD; k++) acc = fmaf(sg[k], l0W[k * DD + t], acc);
    sh[t] = fmaxf(acc, 0.f);
    __syncthreads();
    if (t < OUTC) {
        float a = outb[t];
        #pragma unroll
        for (int k = 0; k < DD; k++) a = fmaf(sh[k], outW[k * OUTC + t], a);
        out[gi * OUTC + t] = a;
    }
}

extern "C" void kernel_launch(void* const* d_in, const int* in_sizes, int n_in,
                              void* d_out, int out_size) {
    const float* x    = (const float*)d_in[0];
    const void*  ei   = d_in[1];
    const void*  bat  = d_in[2];
    const float* c_Wl[3] = { (const float*)d_in[3], (const float*)d_in[6], (const float*)d_in[9]  };
    const float* c_bl[3] = { (const float*)d_in[4], (const float*)d_in[7], (const float*)d_in[10] };
    const float* c_Wr[3] = { (const float*)d_in[5], (const float*)d_in[8], (const float*)d_in[11] };
    const float* l0W  = (const float*)d_in[12];
    const float* l0b  = (const float*)d_in[13];
    const float* outW = (const float*)d_in[14];
    const float* outb = (const float*)d_in[15];
    float* out = (float*)d_out;

    // CSR build
    prep_deg_kernel<<<(EE + 255) / 256, 256>>>(ei, bat);
    scan_block_kernel<<<NB, 256>>>();
    scan_top_kernel<<<1, 512>>>();
    csr_fill_kernel<<<(EE + 255) / 256, 256>>>(ei);

    // 3 SAGE layers: gather-mean then FFMA2 register-tiled linear
    const int gather_blocks = (NN * 32 + 255) / 256;
    const int linear_blocks = (NN + 63) / 64;
    for (int l = 0; l < 3; l++) {
        gather_kernel<<<gather_blocks, 256>>>(l, x);
        linear_kernel<<<linear_blocks, 256>>>(l, x, c_Wl[l], c_bl[l], c_Wr[l]);
    }

    // pooling + MLP
    pool_kernel<<<GG, DD>>>();
    mlp_kernel<<<GG, DD>>>(l0W, l0b, outW, outb, out);
}

// round 13
// speedup vs baseline: 1.0739x; 1.0739x over previous
#include <cuda_runtime.h>

#define NN 100000
#define EE 1600000
#define DD 64
#define GG 64
#define OUTC 10
#define NB ((NN + 255) / 256)   // 391 scan blocks

// ---- scratch ----
__device__ int    g_is64;
__device__ int    g_batch[NN];
__device__ int    g_deg[NN];      // zeroed by trailing fold (and module load)
__device__ int    g_cursor[NN];   // zeroed by trailing fold (and module load)
__device__ int    g_rowstart[NN + 1];
__device__ int    g_bsum[NB];
__device__ int    g_bsum_sc[NB];
__device__ int    g_adj[EE];
__device__ float  g_inv_deg[NN];
__device__ float4 g_agg[(size_t)NN * (DD / 4)];
__device__ float4 g_h0 [(size_t)NN * (DD / 4)];
__device__ float4 g_h1 [(size_t)NN * (DD / 4)];
__device__ float  g_pool[GG * DD];

__device__ __forceinline__ int load_idx(const void* p, size_t i, int is64) {
    return is64 ? (int)((const long long*)p)[i] : ((const int*)p)[i];
}

__device__ __forceinline__ unsigned cvt_tf32(float f) {
    unsigned r; asm("cvt.rna.tf32.f32 %0, %1;" : "=r"(r) : "f"(f)); return r;
}

// m16n8k8 tf32 MMA, fp32 accumulate (legacy mma.sync -> HMMA on sm_103a)
__device__ __forceinline__ void mma_tf32(float* c, const unsigned* a, const unsigned* b) {
    asm("mma.sync.aligned.m16n8k8.row.col.f32.tf32.tf32.f32 "
        "{%0,%1,%2,%3},{%4,%5,%6,%7},{%8,%9},{%0,%1,%2,%3};"
        : "+f"(c[0]), "+f"(c[1]), "+f"(c[2]), "+f"(c[3])
        : "r"(a[0]), "r"(a[1]), "r"(a[2]), "r"(a[3]), "r"(b[0]), "r"(b[1]));
}

// ---- launch 1: dtype detect + batch convert + degree histogram -------------
__global__ void prep_deg_kernel(const void* __restrict__ ei,
                                const void* __restrict__ bat) {
    __shared__ int s_is64;
    if (threadIdx.x == 0) {
        const unsigned int* w = (const unsigned int*)ei;
        int is64 = 1;
        for (int i = 0; i < 16; i++)
            if (w[2 * i + 1] != 0u) { is64 = 0; break; }
        s_is64 = is64;
        if (blockIdx.x == 0) g_is64 = is64;
    }
    __syncthreads();
    int is64 = s_is64;
    int e = blockIdx.x * blockDim.x + threadIdx.x;
    if (e < NN) g_batch[e] = load_idx(bat, e, is64);
    if (e < EE) atomicAdd(&g_deg[load_idx(ei, (size_t)EE + e, is64)], 1);
}

// ---- launch 2: block-local exclusive scan ----------------------------------
__global__ void scan_block_kernel() {
    __shared__ int s[256];
    int tid = threadIdx.x;
    int i = blockIdx.x * 256 + tid;
    int v = (i < NN) ? g_deg[i] : 0;
    s[tid] = v;
    __syncthreads();
    #pragma unroll
    for (int off = 1; off < 256; off <<= 1) {
        int t = (tid >= off) ? s[tid - off] : 0;
        __syncthreads();
        s[tid] += t;
        __syncthreads();
    }
    if (i < NN) g_rowstart[i] = s[tid] - v;
    if (tid == 255) g_bsum[blockIdx.x] = s[255];
}

// ---- launch 3: scan the 391 block sums -------------------------------------
__global__ void scan_top_kernel() {
    __shared__ int s[512];
    int tid = threadIdx.x;
    int v = (tid < NB) ? g_bsum[tid] : 0;
    s[tid] = v;
    __syncthreads();
    #pragma unroll
    for (int off = 1; off < 512; off <<= 1) {
        int t = (tid >= off) ? s[tid - off] : 0;
        __syncthreads();
        s[tid] += t;
        __syncthreads();
    }
    if (tid < NB) g_bsum_sc[tid] = s[tid] - v;
}

// ---- launch 4: materialize global rowstart + inv_deg ------------------------
__global__ void scan_add_kernel() {
    int i = blockIdx.x * 256 + threadIdx.x;
    if (i < NN) {
        g_rowstart[i] += g_bsum_sc[blockIdx.x];
        g_inv_deg[i] = 1.0f / (float)max(g_deg[i], 1);
    }
    if (i == 0) g_rowstart[NN] = EE;
}

// ---- launch 5: adjacency fill (verified near L2-RMW bound: 25us) -----------
__global__ void csr_fill_kernel(const void* __restrict__ ei) {
    int e = blockIdx.x * blockDim.x + threadIdx.x;
    if (e < EE) {
        int is64 = g_is64;
        int src = load_idx(ei, e, is64);
        int dst = load_idx(ei, (size_t)EE + e, is64);
        int pos = atomicAdd(&g_cursor[dst], 1);
        g_adj[g_rowstart[dst] + pos] = src;
    }
}

// ---- gather-mean: one warp per node, lane owns float2, unroll x8 (MLP 8) ---
__global__ void gather_kernel(int sel, const float* __restrict__ x) {
    int gtid = blockIdx.x * blockDim.x + threadIdx.x;
    int node = gtid >> 5;
    if (node >= NN) return;
    int lane = threadIdx.x & 31;

    const float2* hin = (sel == 0) ? (const float2*)x
                       : (sel == 1) ? (const float2*)g_h0 : (const float2*)g_h1;

    int rs = g_rowstart[node];
    int re = g_rowstart[node + 1];
    float ax = 0.f, ay = 0.f;
    int e = rs;
    for (; e + 8 <= re; e += 8) {
        int s0 = g_adj[e+0], s1 = g_adj[e+1], s2 = g_adj[e+2], s3 = g_adj[e+3];
        int s4 = g_adj[e+4], s5 = g_adj[e+5], s6 = g_adj[e+6], s7 = g_adj[e+7];
        float2 v0 = hin[(size_t)s0 * 32 + lane];
        float2 v1 = hin[(size_t)s1 * 32 + lane];
        float2 v2 = hin[(size_t)s2 * 32 + lane];
        float2 v3 = hin[(size_t)s3 * 32 + lane];
        float2 v4 = hin[(size_t)s4 * 32 + lane];
        float2 v5 = hin[(size_t)s5 * 32 + lane];
        float2 v6 = hin[(size_t)s6 * 32 + lane];
        float2 v7 = hin[(size_t)s7 * 32 + lane];
        ax += (v0.x + v1.x) + (v2.x + v3.x) + ((v4.x + v5.x) + (v6.x + v7.x));
        ay += (v0.y + v1.y) + (v2.y + v3.y) + ((v4.y + v5.y) + (v6.y + v7.y));
    }
    for (; e < re; e++) {
        int s = g_adj[e];
        float2 v = hin[(size_t)s * 32 + lane];
        ax += v.x; ay += v.y;
    }
    float inv = g_inv_deg[node];
    ((float2*)g_agg)[(size_t)node * 32 + lane] = make_float2(ax * inv, ay * inv);
}

// ---- tensor-core linear: out = relu([agg|h] @ [Wl;Wr] + bl) ----------------
// 3xTF32 (hi/lo split, fp32 accum -> ~2^-21 error) on mma.sync m16n8k8.
// 256 threads = 8 warps; warp w owns rows [mt*16, mt*16+16) x cols [nh*32,+32)
// (mt = w>>1, nh = w&1), i.e. 4 n8 tiles. K = 2 passes x 2 chunks x 32.
// sA* padded [64][36]: A-frag LDS bank = lane -> conflict-free.
__global__ void linear_kernel(int sel, const float* __restrict__ x,
                              const float* __restrict__ Wl,
                              const float* __restrict__ bl,
                              const float* __restrict__ Wr) {
    __shared__ unsigned sAhi[DD][36], sAlo[DD][36];   // [row][k]
    __shared__ unsigned sWhi[32][68], sWlo[32][68];   // [k][n]
    __shared__ float sb[DD];

    const float* hin  = (sel == 0) ? x
                       : (sel == 1) ? (const float*)g_h0 : (const float*)g_h1;
    float*       hout = (sel == 0) ? (float*)g_h0
                       : (sel == 1) ? (float*)g_h1 : (float*)g_h0;

    int tid  = threadIdx.x;
    int base = blockIdx.x * 64;
    int lane = tid & 31;
    int w    = tid >> 5;
    int mt   = w >> 1;
    int nh   = w & 1;
    if (tid < DD) sb[tid] = bl[tid];

    if (sel == 2 && tid < 64) {          // trailing state-reset fold
        int n = base + tid;
        if (n < NN) { g_deg[n] = 0; g_cursor[n] = 0; }
    }

    float acc[4][4];
    #pragma unroll
    for (int i = 0; i < 4; i++)
        #pragma unroll
        for (int j = 0; j < 4; j++) acc[i][j] = 0.f;

    #pragma unroll
    for (int pass = 0; pass < 2; pass++) {
        const float* A = pass ? hin : (const float*)g_agg;
        const float* W = pass ? Wr : Wl;
        #pragma unroll
        for (int kc = 0; kc < 2; kc++) {
            // stage A chunk [64 rows][32 k] as hi/lo (512 float4, 2/thread)
            #pragma unroll
            for (int u = 0; u < 2; u++) {
                int f = tid * 2 + u;
                int r = f >> 3, c4 = f & 7;
                float4 v = make_float4(0.f, 0.f, 0.f, 0.f);
                if (base + r < NN)
                    v = ((const float4*)A)[(size_t)(base + r) * 16 + kc * 8 + c4];
                float vv[4] = { v.x, v.y, v.z, v.w };
                #pragma unroll
                for (int j = 0; j < 4; j++) {
                    unsigned hi = cvt_tf32(vv[j]);
                    float lo = vv[j] - __uint_as_float(hi);
                    sAhi[r][c4 * 4 + j] = hi;
                    sAlo[r][c4 * 4 + j] = cvt_tf32(lo);
                }
            }
            // stage W chunk [32 k][64 n] as hi/lo (512 float4, 2/thread)
            #pragma unroll
            for (int u = 0; u < 2; u++) {
                int f = tid * 2 + u;
                int kk = f >> 4, n4 = f & 15;
                float4 v = ((const float4*)W)[(size_t)(kc * 32 + kk) * 16 + n4];
                float vv[4] = { v.x, v.y, v.z, v.w };
                #pragma unroll
                for (int j = 0; j < 4; j++) {
                    unsigned hi = cvt_tf32(vv[j]);
                    float lo = vv[j] - __uint_as_float(hi);
                    sWhi[kk][n4 * 4 + j] = hi;
                    sWlo[kk][n4 * 4 + j] = cvt_tf32(lo);
                }
            }
            __syncthreads();
            // 4 k-steps of m16n8k8
            #pragma unroll
            for (int ks = 0; ks < 4; ks++) {
                int kb = ks * 8;
                int r0 = mt * 16 + (lane >> 2);
                int c0 = kb + (lane & 3);
                unsigned ah[4] = { sAhi[r0][c0], sAhi[r0 + 8][c0],
                                   sAhi[r0][c0 + 4], sAhi[r0 + 8][c0 + 4] };
                unsigned al[4] = { sAlo[r0][c0], sAlo[r0 + 8][c0],
                                   sAlo[r0][c0 + 4], sAlo[r0 + 8][c0 + 4] };
                #pragma unroll
                for (int nt = 0; nt < 4; nt++) {
                    int n0 = nh * 32 + nt * 8 + (lane >> 2);
                    int kr = kb + (lane & 3);
                    unsigned bh[2] = { sWhi[kr][n0], sWhi[kr + 4][n0] };
                    unsigned bo[2] = { sWlo[kr][n0], sWlo[kr + 4][n0] };
                    mma_tf32(acc[nt], ah, bh);   // hi*hi
                    mma_tf32(acc[nt], ah, bo);   // hi*lo
                    mma_tf32(acc[nt], al, bh);   // lo*hi
                }
            }
            __syncthreads();
        }
    }

    // epilogue: bias + relu; C frag: rows lane/4 (+8), cols 2*(lane%4) (+1)
    int r0 = base + mt * 16 + (lane >> 2);
    int r1 = r0 + 8;
    #pragma unroll
    for (int nt = 0; nt < 4; nt++) {
        int n0 = nh * 32 + nt * 8;
        int c  = (lane & 3) * 2;
        if (r0 < NN) {
            hout[(size_t)r0 * DD + n0 + c]     = fmaxf(acc[nt][0] + sb[n0 + c],     0.f);
            hout[(size_t)r0 * DD + n0 + c + 1] = fmaxf(acc[nt][1] + sb[n0 + c + 1], 0.f);
        }
        if (r1 < NN) {
            hout[(size_t)r1 * DD + n0 + c]     = fmaxf(acc[nt][2] + sb[n0 + c],     0.f);
            hout[(size_t)r1 * DD + n0 + c + 1] = fmaxf(acc[nt][3] + sb[n0 + c + 1], 0.f);
        }
    }
}

// ---- global mean pool (batch sorted -> binary search) ----------------------
__global__ void pool_kernel() {
    int g = blockIdx.x;
    int col = threadIdx.x;
    int a = 0, b = NN;
    while (a < b) { int m = (a + b) >> 1; if (g_batch[m] < g) a = m + 1; else b = m; }
    int start = a;
    b = NN;
    while (a < b) { int m = (a + b) >> 1; if (g_batch[m] < g + 1) a = m + 1; else b = m; }
    int end = a;
    float acc = 0.f;
    const float* h = (const float*)g_h0;
    for (int n = start; n < end; n++) acc += h[(size_t)n * DD + col];
    g_pool[g * DD + col] = acc / fmaxf((float)(end - start), 1.f);
}

// ---- final MLP -------------------------------------------------------------
__global__ void mlp_kernel(const float* __restrict__ l0W,
                           const float* __restrict__ l0b,
                           const float* __restrict__ outW,
                           const float* __restrict__ outb,
                           float* __restrict__ out) {
    __shared__ float sg[DD];
    __shared__ float sh[DD];
    int gi = blockIdx.x, t = threadIdx.x;
    sg[t] = g_pool[gi * DD + t];
    __syncthreads();
    float acc = l0b[t];
    #pragma unroll
    for (int k = 0; k < DD; k++) acc = fmaf(sg[k], l0W[k * DD + t], acc);
    sh[t] = fmaxf(acc, 0.f);
    __syncthreads();
    if (t < OUTC) {
        float a = outb[t];
        #pragma unroll
        for (int k = 0; k < DD; k++) a = fmaf(sh[k], outW[k * OUTC + t], a);
        out[gi * OUTC + t] = a;
    }
}

extern "C" void kernel_launch(void* const* d_in, const int* in_sizes, int n_in,
                              void* d_out, int out_size) {
    const float* x    = (const float*)d_in[0];
    const void*  ei   = d_in[1];
    const void*  bat  = d_in[2];
    const float* c_Wl[3] = { (const float*)d_in[3], (const float*)d_in[6], (const float*)d_in[9]  };
    const float* c_bl[3] = { (const float*)d_in[4], (const float*)d_in[7], (const float*)d_in[10] };
    const float* c_Wr[3] = { (const float*)d_in[5], (const float*)d_in[8], (const float*)d_in[11] };
    const float* l0W  = (const float*)d_in[12];
    const float* l0b  = (const float*)d_in[13];
    const float* outW = (const float*)d_in[14];
    const float* outb = (const float*)d_in[15];
    float* out = (float*)d_out;

    // CSR build
    prep_deg_kernel<<<(EE + 255) / 256, 256>>>(ei, bat);
    scan_block_kernel<<<NB, 256>>>();
    scan_top_kernel<<<1, 512>>>();
    scan_add_kernel<<<NB, 256>>>();
    csr_fill_kernel<<<(EE + 255) / 256, 256>>>(ei);

    // 3 SAGE layers: gather-mean then 3xTF32 tensor-core linear
    const int gather_blocks = (NN * 32 + 255) / 256;
    const int linear_blocks = (NN + 63) / 64;
    for (int l = 0; l < 3; l++) {
        gather_kernel<<<gather_blocks, 256>>>(l, x);
        linear_kernel<<<linear_blocks, 256>>>(l, x, c_Wl[l], c_bl[l], c_Wr[l]);
    }

    // pooling + MLP
    pool_kernel<<<GG, DD>>>();
    mlp_kernel<<<GG, DD>>>(l0W, l0b, outW, outb, out);
}

// round 14
// speedup vs baseline: 1.1122x; 1.0356x over previous
#include <cuda_runtime.h>
#include <cuda_fp16.h>

#define NN 100000
#define EE 1600000
#define DD 64
#define GG 64
#define OUTC 10
#define NB ((NN + 255) / 256)   // 391 scan blocks

// ---- scratch ----
__device__ int     g_is64;
__device__ int     g_batch[NN];
__device__ int     g_deg[NN];      // zeroed by trailing fold (and module load)
__device__ int     g_cursor[NN];   // zeroed by trailing fold (and module load)
__device__ int     g_rowstart[NN + 1];
__device__ int     g_bsum[NB];
__device__ int     g_bsum_sc[NB];
__device__ int     g_adj[EE];
__device__ float   g_inv_deg[NN];
__device__ float4  g_agg[(size_t)NN * (DD / 4)];
__device__ float4  g_h0 [(size_t)NN * (DD / 4)];
__device__ float4  g_h1 [(size_t)NN * (DD / 4)];
__device__ __half2 g_hh [(size_t)NN * (DD / 2)];   // fp16 mirror of current h
__device__ float   g_pool[GG * DD];

__device__ __forceinline__ int load_idx(const void* p, size_t i, int is64) {
    return is64 ? (int)((const long long*)p)[i] : ((const int*)p)[i];
}

// ---- x -> fp16 mirror (layer-0 gather input) -------------------------------
__global__ void cvt_x_kernel(const float* __restrict__ x) {
    int i = blockIdx.x * blockDim.x + threadIdx.x;
    if (i < NN * (DD / 2)) {
        float2 f = ((const float2*)x)[i];
        g_hh[i] = __floats2half2_rn(f.x, f.y);
    }
}

// ---- dtype detect + batch convert + degree histogram -----------------------
__global__ void prep_deg_kernel(const void* __restrict__ ei,
                                const void* __restrict__ bat) {
    __shared__ int s_is64;
    if (threadIdx.x == 0) {
        const unsigned int* w = (const unsigned int*)ei;
        int is64 = 1;
        for (int i = 0; i < 16; i++)
            if (w[2 * i + 1] != 0u) { is64 = 0; break; }
        s_is64 = is64;
        if (blockIdx.x == 0) g_is64 = is64;
    }
    __syncthreads();
    int is64 = s_is64;
    int e = blockIdx.x * blockDim.x + threadIdx.x;
    if (e < NN) g_batch[e] = load_idx(bat, e, is64);
    if (e < EE) atomicAdd(&g_deg[load_idx(ei, (size_t)EE + e, is64)], 1);
}

// ---- block-local exclusive scan ---------------------------------------------
__global__ void scan_block_kernel() {
    __shared__ int s[256];
    int tid = threadIdx.x;
    int i = blockIdx.x * 256 + tid;
    int v = (i < NN) ? g_deg[i] : 0;
    s[tid] = v;
    __syncthreads();
    #pragma unroll
    for (int off = 1; off < 256; off <<= 1) {
        int t = (tid >= off) ? s[tid - off] : 0;
        __syncthreads();
        s[tid] += t;
        __syncthreads();
    }
    if (i < NN) g_rowstart[i] = s[tid] - v;
    if (tid == 255) g_bsum[blockIdx.x] = s[255];
}

// ---- scan the 391 block sums -------------------------------------------------
__global__ void scan_top_kernel() {
    __shared__ int s[512];
    int tid = threadIdx.x;
    int v = (tid < NB) ? g_bsum[tid] : 0;
    s[tid] = v;
    __syncthreads();
    #pragma unroll
    for (int off = 1; off < 512; off <<= 1) {
        int t = (tid >= off) ? s[tid - off] : 0;
        __syncthreads();
        s[tid] += t;
        __syncthreads();
    }
    if (tid < NB) g_bsum_sc[tid] = s[tid] - v;
}

// ---- materialize global rowstart + inv_deg -----------------------------------
__global__ void scan_add_kernel() {
    int i = blockIdx.x * 256 + threadIdx.x;
    if (i < NN) {
        g_rowstart[i] += g_bsum_sc[blockIdx.x];
        g_inv_deg[i] = 1.0f / (float)max(g_deg[i], 1);
    }
    if (i == 0) g_rowstart[NN] = EE;
}

// ---- adjacency fill (verified near L2-RMW bound: 25us) -----------------------
__global__ void csr_fill_kernel(const void* __restrict__ ei) {
    int e = blockIdx.x * blockDim.x + threadIdx.x;
    if (e < EE) {
        int is64 = g_is64;
        int src = load_idx(ei, e, is64);
        int dst = load_idx(ei, (size_t)EE + e, is64);
        int pos = atomicAdd(&g_cursor[dst], 1);
        g_adj[g_rowstart[dst] + pos] = src;
    }
}

// ---- gather-mean over fp16 neighbor rows ------------------------------------
// One warp per node, lane owns one half2 (2 dims) = 4B -> 128B/row (was 256B).
// fp32 accumulation; unroll x8 keeps MLP 8. L2 read traffic halved.
__global__ void gather_kernel() {
    int gtid = blockIdx.x * blockDim.x + threadIdx.x;
    int node = gtid >> 5;
    if (node >= NN) return;
    int lane = threadIdx.x & 31;

    int rs = g_rowstart[node];
    int re = g_rowstart[node + 1];
    float ax = 0.f, ay = 0.f;
    int e = rs;
    for (; e + 8 <= re; e += 8) {
        int s0 = g_adj[e+0], s1 = g_adj[e+1], s2 = g_adj[e+2], s3 = g_adj[e+3];
        int s4 = g_adj[e+4], s5 = g_adj[e+5], s6 = g_adj[e+6], s7 = g_adj[e+7];
        float2 v0 = __half22float2(g_hh[(size_t)s0 * 32 + lane]);
        float2 v1 = __half22float2(g_hh[(size_t)s1 * 32 + lane]);
        float2 v2 = __half22float2(g_hh[(size_t)s2 * 32 + lane]);
        float2 v3 = __half22float2(g_hh[(size_t)s3 * 32 + lane]);
        float2 v4 = __half22float2(g_hh[(size_t)s4 * 32 + lane]);
        float2 v5 = __half22float2(g_hh[(size_t)s5 * 32 + lane]);
        float2 v6 = __half22float2(g_hh[(size_t)s6 * 32 + lane]);
        float2 v7 = __half22float2(g_hh[(size_t)s7 * 32 + lane]);
        ax += (v0.x + v1.x) + (v2.x + v3.x) + ((v4.x + v5.x) + (v6.x + v7.x));
        ay += (v0.y + v1.y) + (v2.y + v3.y) + ((v4.y + v5.y) + (v6.y + v7.y));
    }
    for (; e < re; e++) {
        int s = g_adj[e];
        float2 v = __half22float2(g_hh[(size_t)s * 32 + lane]);
        ax += v.x; ay += v.y;
    }
    float inv = g_inv_deg[node];
    ((float2*)g_agg)[(size_t)node * 32 + lane] = make_float2(ax * inv, ay * inv);
}

// ---- register-tiled linear: out = relu([agg|h]@[Wl;Wr] + bl) ----------------
// Proven R7 structure: 256 threads = 16x16, 4x4 register tile, two k=64 passes,
// 1 LDS.128 pair per 16 FMAs. Epilogue also writes the fp16 mirror for the
// next layer's gather (skipped on the last layer). sel==2 re-zeros deg/cursor.
__global__ void linear_kernel(int sel, const float* __restrict__ x,
                              const float* __restrict__ Wl,
                              const float* __restrict__ bl,
                              const float* __restrict__ Wr) {
    __shared__ __align__(16) float sA[DD][68];
    __shared__ __align__(16) float sW[DD][DD];
    __shared__ float sb[DD];

    const float* hin  = (sel == 0) ? x
                       : (sel == 1) ? (const float*)g_h0 : (const float*)g_h1;
    float*       hout = (sel == 0) ? (float*)g_h0
                       : (sel == 1) ? (float*)g_h1 : (float*)g_h0;

    int tid  = threadIdx.x;
    int base = blockIdx.x * 64;
    int tc = tid & 15;
    int tr = tid >> 4;
    if (tid < DD) sb[tid] = bl[tid];

    if (sel == 2 && tid < 64) {          // trailing state-reset fold
        int n = base + tid;
        if (n < NN) { g_deg[n] = 0; g_cursor[n] = 0; }
    }

    float acc[4][4];
    #pragma unroll
    for (int i = 0; i < 4; i++)
        #pragma unroll
        for (int j = 0; j < 4; j++) acc[i][j] = 0.f;

    int r_st   = tid >> 2;
    int row_st = base + r_st;
    int k4b    = (tid & 3) * 4;

    #pragma unroll
    for (int pass = 0; pass < 2; pass++) {
        const float* A = (pass == 0) ? (const float*)g_agg : hin;
        const float* W = (pass == 0) ? Wl : Wr;
        for (int i = tid; i < DD * DD; i += 256) sW[i >> 6][i & 63] = W[i];
        #pragma unroll
        for (int j = 0; j < 4; j++) {
            int k4 = k4b + j;
            float4 v = make_float4(0.f, 0.f, 0.f, 0.f);
            if (row_st < NN) v = ((const float4*)A)[(size_t)row_st * (DD/4) + k4];
            sA[k4 * 4 + 0][r_st] = v.x;
            sA[k4 * 4 + 1][r_st] = v.y;
            sA[k4 * 4 + 2][r_st] = v.z;
            sA[k4 * 4 + 3][r_st] = v.w;
        }
        __syncthreads();
        #pragma unroll 8
        for (int k = 0; k < DD; k++) {
            float4 a4 = *(const float4*)&sA[k][tr * 4];
            float4 w4 = *(const float4*)&sW[k][tc * 4];
            float av[4] = { a4.x, a4.y, a4.z, a4.w };
            float wv[4] = { w4.x, w4.y, w4.z, w4.w };
            #pragma unroll
            for (int i = 0; i < 4; i++)
                #pragma unroll
                for (int j = 0; j < 4; j++)
                    acc[i][j] = fmaf(av[i], wv[j], acc[i][j]);
        }
        __syncthreads();
    }

    #pragma unroll
    for (int i = 0; i < 4; i++) {
        int row = base + tr * 4 + i;
        if (row < NN) {
            float4 o;
            o.x = fmaxf(acc[i][0] + sb[tc * 4 + 0], 0.f);
            o.y = fmaxf(acc[i][1] + sb[tc * 4 + 1], 0.f);
            o.z = fmaxf(acc[i][2] + sb[tc * 4 + 2], 0.f);
            o.w = fmaxf(acc[i][3] + sb[tc * 4 + 3], 0.f);
            *(float4*)&hout[(size_t)row * DD + tc * 4] = o;
            if (sel != 2) {              // fp16 mirror for next layer's gather
                g_hh[(size_t)row * 32 + tc * 2 + 0] = __floats2half2_rn(o.x, o.y);
                g_hh[(size_t)row * 32 + tc * 2 + 1] = __floats2half2_rn(o.z, o.w);
            }
        }
    }
}

// ---- global mean pool (batch sorted -> binary search) ------------------------
__global__ void pool_kernel() {
    int g = blockIdx.x;
    int col = threadIdx.x;
    int a = 0, b = NN;
    while (a < b) { int m = (a + b) >> 1; if (g_batch[m] < g) a = m + 1; else b = m; }
    int start = a;
    b = NN;
    while (a < b) { int m = (a + b) >> 1; if (g_batch[m] < g + 1) a = m + 1; else b = m; }
    int end = a;
    float acc = 0.f;
    const float* h = (const float*)g_h0;
    for (int n = start; n < end; n++) acc += h[(size_t)n * DD + col];
    g_pool[g * DD + col] = acc / fmaxf((float)(end - start), 1.f);
}

// ---- final MLP ----------------------------------------------------------------
__global__ void mlp_kernel(const float* __restrict__ l0W,
                           const float* __restrict__ l0b,
                           const float* __restrict__ outW,
                           const float* __restrict__ outb,
                           float* __restrict__ out) {
    __shared__ float sg[DD];
    __shared__ float sh[DD];
    int gi = blockIdx.x, t = threadIdx.x;
    sg[t] = g_pool[gi * DD + t];
    __syncthreads();
    float acc = l0b[t];
    #pragma unroll
    for (int k = 0; k < DD; k++) acc = fmaf(sg[k], l0W[k * DD + t], acc);
    sh[t] = fmaxf(acc, 0.f);
    __syncthreads();
    if (t < OUTC) {
        float a = outb[t];
        #pragma unroll
        for (int k = 0; k < DD; k++) a = fmaf(sh[k], outW[k * OUTC + t], a);
        out[gi * OUTC + t] = a;
    }
}

extern "C" void kernel_launch(void* const* d_in, const int* in_sizes, int n_in,
                              void* d_out, int out_size) {
    const float* x    = (const float*)d_in[0];
    const void*  ei   = d_in[1];
    const void*  bat  = d_in[2];
    const float* c_Wl[3] = { (const float*)d_in[3], (const float*)d_in[6], (const float*)d_in[9]  };
    const float* c_bl[3] = { (const float*)d_in[4], (const float*)d_in[7], (const float*)d_in[10] };
    const float* c_Wr[3] = { (const float*)d_in[5], (const float*)d_in[8], (const float*)d_in[11] };
    const float* l0W  = (const float*)d_in[12];
    const float* l0b  = (const float*)d_in[13];
    const float* outW = (const float*)d_in[14];
    const float* outb = (const float*)d_in[15];
    float* out = (float*)d_out;

    // CSR build + fp16 mirror of x
    prep_deg_kernel<<<(EE + 255) / 256, 256>>>(ei, bat);
    scan_block_kernel<<<NB, 256>>>();
    scan_top_kernel<<<1, 512>>>();
    scan_add_kernel<<<NB, 256>>>();
    csr_fill_kernel<<<(EE + 255) / 256, 256>>>(ei);
    cvt_x_kernel<<<(NN * (DD / 2) + 255) / 256, 256>>>(x);

    // 3 SAGE layers: fp16 gather-mean then fp32 register-tiled linear
    const int gather_blocks = (NN * 32 + 255) / 256;
    const int linear_blocks = (NN + 63) / 64;
    for (int l = 0; l < 3; l++) {
        gather_kernel<<<gather_blocks, 256>>>();
        linear_kernel<<<linear_blocks, 256>>>(l, x, c_Wl[l], c_bl[l], c_Wr[l]);
    }

    // pooling + MLP
    pool_kernel<<<GG, DD>>>();
    mlp_kernel<<<GG, DD>>>(l0W, l0b, outW, outb, out);
}

// round 16
// speedup vs baseline: 1.1168x; 1.0042x over previous
#include <cuda_runtime.h>
#include <cuda_fp16.h>

#define NN 100000
#define EE 1600000
#define DD 64
#define GG 64
#define OUTC 10
#define NB ((NN + 255) / 256)   // 391 scan blocks

// ---- scratch ----
__device__ int     g_is64;
__device__ int     g_batch[NN];
__device__ int     g_deg[NN];      // zeroed by trailing fold (and module load)
__device__ int     g_cursor[NN];   // zeroed by trailing fold (and module load)
__device__ int     g_rowstart[NN + 1];
__device__ unsigned long long g_scan_state[NB];  // lookback: flag(2b)<<62 | value
__device__ int     g_adj[EE];
__device__ float   g_inv_deg[NN];
__device__ float4  g_agg[(size_t)NN * (DD / 4)];
__device__ float4  g_h0 [(size_t)NN * (DD / 4)];
__device__ float4  g_h1 [(size_t)NN * (DD / 4)];
__device__ __half2 g_hh [(size_t)NN * (DD / 2)];   // fp16 mirror of current h
__device__ float   g_pool[GG * DD];

__device__ __forceinline__ int load_idx(const void* p, size_t i, int is64) {
    return is64 ? (int)((const long long*)p)[i] : ((const int*)p)[i];
}

// ---- launch 1: dtype detect + batch cvt + degree histogram + x->fp16 + state reset
// GRID MUST COVER NN*(DD/2)=3.2M threads (R15 bug: sized on EE=1.6M, leaving
// half the fp16 mirror of x stale -> rel_err 1.7e-2).
__global__ void prep_deg_kernel(const void* __restrict__ ei,
                                const void* __restrict__ bat,
                                const float* __restrict__ x) {
    __shared__ int s_is64;
    if (threadIdx.x == 0) {
        const unsigned int* w = (const unsigned int*)ei;
        int is64 = 1;
        for (int i = 0; i < 16; i++)
            if (w[2 * i + 1] != 0u) { is64 = 0; break; }
        s_is64 = is64;
        if (blockIdx.x == 0) g_is64 = is64;
    }
    __syncthreads();
    int is64 = s_is64;
    int e = blockIdx.x * blockDim.x + threadIdx.x;
    if (e < NB) g_scan_state[e] = 0ull;              // reset lookback state per call
    if (e < NN) g_batch[e] = load_idx(bat, e, is64);
    if (e < NN * (DD / 2)) {                          // fp16 mirror of x
        float2 f = ((const float2*)x)[e];
        g_hh[e] = __floats2half2_rn(f.x, f.y);
    }
    if (e < EE) atomicAdd(&g_deg[load_idx(ei, (size_t)EE + e, is64)], 1);
}

// ---- launch 2: single-pass exclusive scan (decoupled lookback) --------------
// Flag+value share one 64-bit word -> single atomic word, no fence needed.
// All 391 blocks co-resident (<< 148*32) -> lookback cannot deadlock.
#define FLAG_AGG  (1ull << 62)
#define FLAG_PREF (2ull << 62)
__global__ void scan_kernel() {
    __shared__ int s[256];
    __shared__ int s_excl;
    int tid = threadIdx.x;
    int bid = blockIdx.x;
    int i = bid * 256 + tid;
    int v = (i < NN) ? g_deg[i] : 0;
    s[tid] = v;
    __syncthreads();
    #pragma unroll
    for (int off = 1; off < 256; off <<= 1) {
        int t = (tid >= off) ? s[tid - off] : 0;
        __syncthreads();
        s[tid] += t;
        __syncthreads();
    }
    if (tid == 0) {
        int total = s[255];
        if (bid == 0) {
            atomicExch(&g_scan_state[0], FLAG_PREF | (unsigned)total);
            s_excl = 0;
        } else {
            atomicExch(&g_scan_state[bid], FLAG_AGG | (unsigned)total);
            int excl = 0;
            int j = bid - 1;
            while (true) {
                unsigned long long st =
                    *(volatile unsigned long long*)&g_scan_state[j];
                if (!(st >> 62)) { __nanosleep(20); continue; }
                excl += (int)(st & 0xFFFFFFFFu);
                if (st & FLAG_PREF) break;
                j--;
            }
            atomicExch(&g_scan_state[bid], FLAG_PREF | (unsigned)(excl + total));
            s_excl = excl;
        }
    }
    __syncthreads();
    int ex = s_excl;
    if (i < NN) {
        g_rowstart[i] = ex + s[tid] - v;              // global exclusive
        g_inv_deg[i] = 1.0f / (float)max(v, 1);
    }
    if (i == 0) g_rowstart[NN] = EE;
}

// ---- launch 3: adjacency fill (verified near L2-RMW bound: 25us) ------------
__global__ void csr_fill_kernel(const void* __restrict__ ei) {
    int e = blockIdx.x * blockDim.x + threadIdx.x;
    if (e < EE) {
        int is64 = g_is64;
        int src = load_idx(ei, e, is64);
        int dst = load_idx(ei, (size_t)EE + e, is64);
        int pos = atomicAdd(&g_cursor[dst], 1);
        g_adj[g_rowstart[dst] + pos] = src;
    }
}

// ---- launch 4 (PROFILED): gather-mean over fp16 rows ------------------------
// One warp per node, lane owns one half2 (128B/row), fp32 accumulation, MLP 8.
__global__ void gather_kernel() {
    int gtid = blockIdx.x * blockDim.x + threadIdx.x;
    int node = gtid >> 5;
    if (node >= NN) return;
    int lane = threadIdx.x & 31;

    int rs = g_rowstart[node];
    int re = g_rowstart[node + 1];
    float ax = 0.f, ay = 0.f;
    int e = rs;
    for (; e + 8 <= re; e += 8) {
        int s0 = g_adj[e+0], s1 = g_adj[e+1], s2 = g_adj[e+2], s3 = g_adj[e+3];
        int s4 = g_adj[e+4], s5 = g_adj[e+5], s6 = g_adj[e+6], s7 = g_adj[e+7];
        float2 v0 = __half22float2(g_hh[(size_t)s0 * 32 + lane]);
        float2 v1 = __half22float2(g_hh[(size_t)s1 * 32 + lane]);
        float2 v2 = __half22float2(g_hh[(size_t)s2 * 32 + lane]);
        float2 v3 = __half22float2(g_hh[(size_t)s3 * 32 + lane]);
        float2 v4 = __half22float2(g_hh[(size_t)s4 * 32 + lane]);
        float2 v5 = __half22float2(g_hh[(size_t)s5 * 32 + lane]);
        float2 v6 = __half22float2(g_hh[(size_t)s6 * 32 + lane]);
        float2 v7 = __half22float2(g_hh[(size_t)s7 * 32 + lane]);
        ax += (v0.x + v1.x) + (v2.x + v3.x) + ((v4.x + v5.x) + (v6.x + v7.x));
        ay += (v0.y + v1.y) + (v2.y + v3.y) + ((v4.y + v5.y) + (v6.y + v7.y));
    }
    for (; e < re; e++) {
        int s = g_adj[e];
        float2 v = __half22float2(g_hh[(size_t)s * 32 + lane]);
        ax += v.x; ay += v.y;
    }
    float inv = g_inv_deg[node];
    ((float2*)g_agg)[(size_t)node * 32 + lane] = make_float2(ax * inv, ay * inv);
}

// ---- register-tiled linear: out = relu([agg|h]@[Wl;Wr] + bl) ----------------
// 256 threads = 16x16, 4x4 register tile, two k=64 passes. Epilogue writes the
// fp16 mirror for the next layer (skipped on last). sel==2 re-zeros deg/cursor.
__global__ void linear_kernel(int sel, const float* __restrict__ x,
                              const float* __restrict__ Wl,
                              const float* __restrict__ bl,
                              const float* __restrict__ Wr) {
    __shared__ __align__(16) float sA[DD][68];
    __shared__ __align__(16) float sW[DD][DD];
    __shared__ float sb[DD];

    const float* hin  = (sel == 0) ? x
                       : (sel == 1) ? (const float*)g_h0 : (const float*)g_h1;
    float*       hout = (sel == 0) ? (float*)g_h0
                       : (sel == 1) ? (float*)g_h1 : (float*)g_h0;

    int tid  = threadIdx.x;
    int base = blockIdx.x * 64;
    int tc = tid & 15;
    int tr = tid >> 4;
    if (tid < DD) sb[tid] = bl[tid];

    if (sel == 2 && tid < 64) {          // trailing state-reset fold
        int n = base + tid;
        if (n < NN) { g_deg[n] = 0; g_cursor[n] = 0; }
    }

    float acc[4][4];
    #pragma unroll
    for (int i = 0; i < 4; i++)
        #pragma unroll
        for (int j = 0; j < 4; j++) acc[i][j] = 0.f;

    int r_st   = tid >> 2;
    int row_st = base + r_st;
    int k4b    = (tid & 3) * 4;

    #pragma unroll
    for (int pass = 0; pass < 2; pass++) {
        const float* A = (pass == 0) ? (const float*)g_agg : hin;
        const float* W = (pass == 0) ? Wl : Wr;
        for (int i = tid; i < DD * DD; i += 256) sW[i >> 6][i & 63] = W[i];
        #pragma unroll
        for (int j = 0; j < 4; j++) {
            int k4 = k4b + j;
            float4 v = make_float4(0.f, 0.f, 0.f, 0.f);
            if (row_st < NN) v = ((const float4*)A)[(size_t)row_st * (DD/4) + k4];
            sA[k4 * 4 + 0][r_st] = v.x;
            sA[k4 * 4 + 1][r_st] = v.y;
            sA[k4 * 4 + 2][r_st] = v.z;
            sA[k4 * 4 + 3][r_st] = v.w;
        }
        __syncthreads();
        #pragma unroll 8
        for (int k = 0; k < DD; k++) {
            float4 a4 = *(const float4*)&sA[k][tr * 4];
            float4 w4 = *(const float4*)&sW[k][tc * 4];
            float av[4] = { a4.x, a4.y, a4.z, a4.w };
            float wv[4] = { w4.x, w4.y, w4.z, w4.w };
            #pragma unroll
            for (int i = 0; i < 4; i++)
                #pragma unroll
                for (int j = 0; j < 4; j++)
                    acc[i][j] = fmaf(av[i], wv[j], acc[i][j]);
        }
        __syncthreads();
    }

    #pragma unroll
    for (int i = 0; i < 4; i++) {
        int row = base + tr * 4 + i;
        if (row < NN) {
            float4 o;
            o.x = fmaxf(acc[i][0] + sb[tc * 4 + 0], 0.f);
            o.y = fmaxf(acc[i][1] + sb[tc * 4 + 1], 0.f);
            o.z = fmaxf(acc[i][2] + sb[tc * 4 + 2], 0.f);
            o.w = fmaxf(acc[i][3] + sb[tc * 4 + 3], 0.f);
            *(float4*)&hout[(size_t)row * DD + tc * 4] = o;
            if (sel != 2) {
                g_hh[(size_t)row * 32 + tc * 2 + 0] = __floats2half2_rn(o.x, o.y);
                g_hh[(size_t)row * 32 + tc * 2 + 1] = __floats2half2_rn(o.z, o.w);
            }
        }
    }
}

// ---- global mean pool (batch sorted -> binary search) -----------------------
__global__ void pool_kernel() {
    int g = blockIdx.x;
    int col = threadIdx.x;
    int a = 0, b = NN;
    while (a < b) { int m = (a + b) >> 1; if (g_batch[m] < g) a = m + 1; else b = m; }
    int start = a;
    b = NN;
    while (a < b) { int m = (a + b) >> 1; if (g_batch[m] < g + 1) a = m + 1; else b = m; }
    int end = a;
    float acc = 0.f;
    const float* h = (const float*)g_h0;
    for (int n = start; n < end; n++) acc += h[(size_t)n * DD + col];
    g_pool[g * DD + col] = acc / fmaxf((float)(end - start), 1.f);
}

// ---- final MLP --------------------------------------------------------------
__global__ void mlp_kernel(const float* __restrict__ l0W,
                           const float* __restrict__ l0b,
                           const float* __restrict__ outW,
                           const float* __restrict__ outb,
                           float* __restrict__ out) {
    __shared__ float sg[DD];
    __shared__ float sh[DD];
    int gi = blockIdx.x, t = threadIdx.x;
    sg[t] = g_pool[gi * DD + t];
    __syncthreads();
    float acc = l0b[t];
    #pragma unroll
    for (int k = 0; k < DD; k++) acc = fmaf(sg[k], l0W[k * DD + t], acc);
    sh[t] = fmaxf(acc, 0.f);
    __syncthreads();
    if (t < OUTC) {
        float a = outb[t];
        #pragma unroll
        for (int k = 0; k < DD; k++) a = fmaf(sh[k], outW[k * OUTC + t], a);
        out[gi * OUTC + t] = a;
    }
}

extern "C" void kernel_launch(void* const* d_in, const int* in_sizes, int n_in,
                              void* d_out, int out_size) {
    const float* x    = (const float*)d_in[0];
    const void*  ei   = d_in[1];
    const void*  bat  = d_in[2];
    const float* c_Wl[3] = { (const float*)d_in[3], (const float*)d_in[6], (const float*)d_in[9]  };
    const float* c_bl[3] = { (const float*)d_in[4], (const float*)d_in[7], (const float*)d_in[10] };
    const float* c_Wr[3] = { (const float*)d_in[5], (const float*)d_in[8], (const float*)d_in[11] };
    const float* l0W  = (const float*)d_in[12];
    const float* l0b  = (const float*)d_in[13];
    const float* outW = (const float*)d_in[14];
    const float* outb = (const float*)d_in[15];
    float* out = (float*)d_out;

    // CSR build: 3 launches, so gather L0 sits in the profiler window (slot 4)
    const int prep_blocks = (NN * (DD / 2) + 255) / 256;   // covers the 3.2M cvt threads
    prep_deg_kernel<<<prep_blocks, 256>>>(ei, bat, x);
    scan_kernel<<<NB, 256>>>();
    csr_fill_kernel<<<(EE + 255) / 256, 256>>>(ei);

    // 3 SAGE layers: fp16 gather-mean then fp32 register-tiled linear
    const int gather_blocks = (NN * 32 + 255) / 256;
    const int linear_blocks = (NN + 63) / 64;
    for (int l = 0; l < 3; l++) {
        gather_kernel<<<gather_blocks, 256>>>();
        linear_kernel<<<linear_blocks, 256>>>(l, x, c_Wl[l], c_bl[l], c_Wr[l]);
    }

    // pooling + MLP
    pool_kernel<<<GG, DD>>>();
    mlp_kernel<<<GG, DD>>>(l0W, l0b, outW, outb, out);
}